// round 6
// baseline (speedup 1.0000x reference)
#include <cuda_runtime.h>
#include <cstdint>

#define FULLMASK 0xffffffffu
typedef unsigned long long ull;

static constexpr int Hh     = 5;
static constexpr int Tt     = 512;
static constexpr int Bb     = 8192;
static constexpr int CHUNK  = 8;            // timesteps per smem chunk
static constexpr int NCHUNK = Tt / CHUNK;   // 64
static constexpr int SLOTS  = 6;            // element-PAIRS per block
static constexpr int EPB    = 2 * SLOTS;    // 12 elements per block
static constexpr int BLOCK  = 32;           // one warp per block
static constexpr int GRID   = (Bb + EPB - 1) / EPB;   // 683
static constexpr int ROWF   = Tt * Hh;      // 2560
static constexpr int STAGE_N = EPB * CHUNK * Hh;      // 480 floats / chunk
static constexpr int PF      = STAGE_N / BLOCK;       // 15

// ---------- packed f32x2 helpers ----------
__device__ __forceinline__ ull pack2(float lo, float hi) {
    ull r; asm("mov.b64 %0, {%1, %2};" : "=l"(r) : "f"(lo), "f"(hi)); return r;
}
__device__ __forceinline__ void unpack2(ull v, float& lo, float& hi) {
    asm("mov.b64 {%0, %1}, %2;" : "=f"(lo), "=f"(hi) : "l"(v));
}
__device__ __forceinline__ ull fma2(ull a, ull b, ull c) {
    ull d; asm("fma.rn.f32x2 %0, %1, %2, %3;" : "=l"(d) : "l"(a), "l"(b), "l"(c));
    return d;
}
__device__ __forceinline__ ull dup2(float v) { return pack2(v, v); }
__device__ __forceinline__ float tanh_fast(float x) {
    float y; asm("tanh.approx.f32 %0, %1;" : "=f"(y) : "f"(x)); return y;
}

// ============================================================================
// Fused LSTM + head. One warp per block. 6 slots * 5 subs = 30 lanes; each
// slot = TWO batch elements (A,B) packed in f32x2 lanes. Thread (slot,sub)
// owns gate rows {i,f,g,o} component `sub` for both elements.
// Sigmoid folding (as before): acc_i/f/o = 0.5*z; internal state hs = 2*h
// (W_ih i/f/o *0.5, W_hh i/f/o *0.25, W_hh g *0.5; biases likewise).
// ============================================================================
__global__ void __launch_bounds__(BLOCK)
fused_kernel(const float* __restrict__ x,
             const float* __restrict__ W_ih, const float* __restrict__ W_hh,
             const float* __restrict__ b_ih, const float* __restrict__ b_hh,
             const float* __restrict__ W1, const float* __restrict__ b1,
             const float* __restrict__ W2, const float* __restrict__ b2,
             const float* __restrict__ W3, const float* __restrict__ b3,
             float* __restrict__ out)
{
    __shared__ ull sx[2][CHUNK][SLOTS][Hh];          // x pairs (A,B): 3840 B
    __shared__ float sW1[32 * 5], sb1[32], sb2[32], sb3[5];
    __shared__ float sW2[32 * 33];                   // padded rows
    __shared__ float sW3[5 * 33];
    __shared__ float hres[EPB * Hh];                 // residual-added h

    const int lane = threadIdx.x;
    int s = lane / 5, sub = lane % 5;
    const bool lane_ok = (lane < 30);
    if (!lane_ok) { s = 5; sub = 0; }                // lanes 30/31 mirror slot 5

    const int base = blockIdx.x * EPB;
    const int eA = base + 2 * s;                     // elements of this slot
    const int eB = eA + 1;

    // ---- weights: scalar, duplicated into both f32x2 lanes (40 ull) ----
    ull wIx[5], wFx[5], wGx[5], wOx[5], wIh[5], wFh[5], wGh[5], wOh[5];
#pragma unroll
    for (int k = 0; k < 5; ++k) {
        wIx[k] = dup2(0.50f * W_ih[(sub     ) * 5 + k]);
        wFx[k] = dup2(0.50f * W_ih[(sub + 5 ) * 5 + k]);
        wGx[k] = dup2(        W_ih[(sub + 10) * 5 + k]);
        wOx[k] = dup2(0.50f * W_ih[(sub + 15) * 5 + k]);
        wIh[k] = dup2(0.25f * W_hh[(sub     ) * 5 + k]);
        wFh[k] = dup2(0.25f * W_hh[(sub + 5 ) * 5 + k]);
        wGh[k] = dup2(0.50f * W_hh[(sub + 10) * 5 + k]);
        wOh[k] = dup2(0.25f * W_hh[(sub + 15) * 5 + k]);
    }
    const ull bI = dup2(0.5f * (b_ih[sub     ] + b_hh[sub     ]));
    const ull bF = dup2(0.5f * (b_ih[sub + 5 ] + b_hh[sub + 5 ]));
    const ull bG = dup2(       (b_ih[sub + 10] + b_hh[sub + 10]));
    const ull bO = dup2(0.5f * (b_ih[sub + 15] + b_hh[sub + 15]));

    // ---- head weights to smem (one-time; overlaps with nothing critical) ----
    for (int i = lane; i < 160; i += BLOCK) sW1[i] = W1[i];
    for (int i = lane; i < 1024; i += BLOCK) sW2[(i >> 5) * 33 + (i & 31)] = W2[i];
    for (int i = lane; i < 160; i += BLOCK) sW3[(i >> 5) * 33 + (i & 31)] = W3[i];
    if (lane < 32) { sb1[lane] = b1[lane]; sb2[lane] = b2[lane]; }
    if (lane < 5)  sb3[lane] = b3[lane];

    // ---- stage chunk 0 ----
    {
        float* dst = (float*)&sx[0][0][0][0];
#pragma unroll
        for (int it = 0; it < PF; ++it) {
            const int i = lane + it * BLOCK;
            const int e = i / 40, r = i - e * 40;
            const int gb = base + e;
            const float v = (gb < Bb) ? x[gb * ROWF + r] : 0.0f;
            const int t = r / 5, k = r - t * 5;
            dst[((t * SLOTS + (e >> 1)) * Hh + k) * 2 + (e & 1)] = v;
        }
    }
    __syncwarp();

    ull   hs2 = 0;            // (2*hA, 2*hB)
    float cA = 0.0f, cB = 0.0f;

    for (int ch = 0; ch < NCHUNK; ++ch) {
        // prefetch next chunk (LDG latency hidden behind 8 recurrent steps)
        float pf[PF];
        if (ch + 1 < NCHUNK) {
#pragma unroll
            for (int it = 0; it < PF; ++it) {
                const int i = lane + it * BLOCK;
                const int e = i / 40, r = i - e * 40;
                const int gb = base + e;
                pf[it] = (gb < Bb) ? x[gb * ROWF + (ch + 1) * 40 + r] : 0.0f;
            }
        }

#pragma unroll
        for (int tl = 0; tl < CHUNK; ++tl) {
            const ull* xr = &sx[ch & 1][tl][s][0];
            ull aI = bI, aF = bF, aG = bG, aO = bO;
#pragma unroll
            for (int k = 0; k < 5; ++k) {
                const ull xk = xr[k];                 // (xA_k, xB_k) one LDS.64
                aI = fma2(wIx[k], xk, aI);
                aF = fma2(wFx[k], xk, aF);
                aG = fma2(wGx[k], xk, aG);
                aO = fma2(wOx[k], xk, aO);
            }
#pragma unroll
            for (int k = 0; k < 5; ++k) {
                const ull hk = __shfl_sync(FULLMASK, hs2, s * 5 + k); // 2 SHFL
                aI = fma2(wIh[k], hk, aI);
                aF = fma2(wFh[k], hk, aF);
                aG = fma2(wGh[k], hk, aG);
                aO = fma2(wOh[k], hk, aO);
            }
            float ziA, ziB, zfA, zfB, zgA, zgB, zoA, zoB;
            unpack2(aI, ziA, ziB); unpack2(aF, zfA, zfB);
            unpack2(aG, zgA, zgB); unpack2(aO, zoA, zoB);

            // element A
            {
                const float Ti = tanh_fast(ziA), Tf = tanh_fast(zfA);
                const float Tg = tanh_fast(zgA), To = tanh_fast(zoA);
                const float u = fmaf(Tf, cA, cA);     // 2*f*c
                const float v = fmaf(Ti, Tg, Tg);     // 2*i*g
                cA = 0.5f * (u + v);
                const float Tc = tanh_fast(cA);
                ziA = fmaf(To, Tc, Tc);               // new hsA
            }
            // element B
            {
                const float Ti = tanh_fast(ziB), Tf = tanh_fast(zfB);
                const float Tg = tanh_fast(zgB), To = tanh_fast(zoB);
                const float u = fmaf(Tf, cB, cB);
                const float v = fmaf(Ti, Tg, Tg);
                cB = 0.5f * (u + v);
                const float Tc = tanh_fast(cB);
                ziB = fmaf(To, Tc, Tc);               // new hsB
            }
            hs2 = pack2(ziA, ziB);                    // single pack per step
        }

        if (ch + 1 < NCHUNK) {
            float* dst = (float*)&sx[(ch + 1) & 1][0][0][0];
#pragma unroll
            for (int it = 0; it < PF; ++it) {
                const int i = lane + it * BLOCK;
                const int e = i / 40, r = i - e * 40;
                const int t = r / 5, k = r - t * 5;
                dst[((t * SLOTS + (e >> 1)) * Hh + k) * 2 + (e & 1)] = pf[it];
            }
        }
        __syncwarp();
    }

    // ==================== fused head ====================
    {
        float hsA, hsB; unpack2(hs2, hsA, hsB);
        if (lane_ok) {
            if (eA < Bb)
                hres[(2 * s    ) * Hh + sub] = 0.5f * hsA + x[eA * ROWF + (Tt - 1) * Hh + sub];
            if (eB < Bb)
                hres[(2 * s + 1) * Hh + sub] = 0.5f * hsB + x[eB * ROWF + (Tt - 1) * Hh + sub];
        }
    }
    __syncwarp();

    for (int e = 0; e < EPB; ++e) {
        const int gb = base + e;
        float a1 = sb1[lane];
#pragma unroll
        for (int k = 0; k < 5; ++k)
            a1 = fmaf(sW1[lane * 5 + k], hres[e * Hh + k], a1);  // LDS broadcast
        a1 = fmaxf(a1, 0.0f);

        float a2 = sb2[lane];
#pragma unroll
        for (int k = 0; k < 32; ++k)
            a2 = fmaf(sW2[lane * 33 + k], __shfl_sync(FULLMASK, a1, k), a2);
        a2 = fmaxf(a2, 0.0f);

        const int wrow = (lane < 5) ? lane : 0;
        float o = (lane < 5) ? sb3[lane] : 0.0f;
#pragma unroll
        for (int k = 0; k < 32; ++k)
            o = fmaf(sW3[wrow * 33 + k], __shfl_sync(FULLMASK, a2, k), o);

        if (lane < 5 && gb < Bb) out[gb * Hh + lane] = o;
    }
}

// ============================================================================
extern "C" void kernel_launch(void* const* d_in, const int* in_sizes, int n_in,
                              void* d_out, int out_size) {
    const float* x    = (const float*)d_in[0];
    const float* W_ih = (const float*)d_in[1];
    const float* W_hh = (const float*)d_in[2];
    const float* b_ih = (const float*)d_in[3];
    const float* b_hh = (const float*)d_in[4];
    const float* W1   = (const float*)d_in[5];
    const float* b1   = (const float*)d_in[6];
    const float* W2   = (const float*)d_in[7];
    const float* b2   = (const float*)d_in[8];
    const float* W3   = (const float*)d_in[9];
    const float* b3   = (const float*)d_in[10];
    float* out = (float*)d_out;

    fused_kernel<<<GRID, BLOCK>>>(x, W_ih, W_hh, b_ih, b_hh,
                                  W1, b1, W2, b2, W3, b3, out);
    (void)in_sizes; (void)n_in; (void)out_size;
}

// round 8
// speedup vs baseline: 1.2073x; 1.2073x over previous
#include <cuda_runtime.h>
#include <cstdint>

#define FULLMASK 0xffffffffu
typedef unsigned long long ull;

static constexpr int Hh     = 5;
static constexpr int Tt     = 512;
static constexpr int Bb     = 8192;
static constexpr int CHUNK  = 16;           // timesteps per smem chunk
static constexpr int NCHUNK = Tt / CHUNK;   // 32
static constexpr int EPW    = 3;            // elements per warp (10 lanes each)
static constexpr int BLOCK  = 32;
static constexpr int GRID   = (Bb + EPW - 1) / EPW;   // 2731
static constexpr int ROWF   = Tt * Hh;      // 2560
static constexpr int CH_FL  = CHUNK * Hh;   // 80 floats per element per chunk
static constexpr int Q4     = EPW * CH_FL / 4;        // 60 float4 per chunk

// ---------- packed f32x2 helpers ----------
__device__ __forceinline__ ull pack2(float lo, float hi) {
    ull r; asm("mov.b64 %0, {%1, %2};" : "=l"(r) : "f"(lo), "f"(hi)); return r;
}
__device__ __forceinline__ void unpack2(ull v, float& lo, float& hi) {
    asm("mov.b64 {%0, %1}, %2;" : "=f"(lo), "=f"(hi) : "l"(v));
}
__device__ __forceinline__ ull fma2(ull a, ull b, ull c) {
    ull d; asm("fma.rn.f32x2 %0, %1, %2, %3;" : "=l"(d) : "l"(a), "l"(b), "l"(c));
    return d;
}
__device__ __forceinline__ float tanh_fast(float x) {
    float y; asm("tanh.approx.f32 %0, %1;" : "=f"(y) : "f"(x)); return y;
}

// ============================================================================
// Fused LSTM + head. One warp per CTA, 3 elements per warp, 10 lanes/element.
// Lane (e, half, sub):  half0 owns gate rows (i_sub, g_sub) as an f32x2 pair,
//                       half1 owns (f_sub, o_sub) and the state c[sub], hs[sub].
// Sigmoid folding: acc for i/f/o rows = z/2 ; internal state hs = 2*h.
//   i = 0.5*tanh(zi/2)+0.5  etc.  =>  2ig = fma(Ti,Tg,Tg); 2fc = fma(Tf,c,c);
//   c' = 0.5*(2fc + 2ig);  hs' = fma(To,Tc,Tc).
// Weight pre-scales: W_ih: i/f/o *0.5, g *1 ; W_hh: i/f/o *0.25, g *0.5.
// ============================================================================
__global__ void __launch_bounds__(BLOCK)
fused_kernel(const float* __restrict__ x,
             const float* __restrict__ W_ih, const float* __restrict__ W_hh,
             const float* __restrict__ b_ih, const float* __restrict__ b_hh,
             const float* __restrict__ W1, const float* __restrict__ b1,
             const float* __restrict__ W2, const float* __restrict__ b2,
             const float* __restrict__ W3, const float* __restrict__ b3,
             float* __restrict__ out)
{
    __shared__ ull   sx[2][CHUNK][EPW][Hh];   // x duplicated (v,v): 3840 B
    __shared__ float sW1[32 * 5], sb1[32], sb2[32], sb3[5];
    __shared__ float sW2[32 * 33];            // padded rows (no 32-way conflict)
    __shared__ float sW3[5 * 33];
    __shared__ float hres[EPW * Hh];

    const int lane = threadIdx.x;
    int r10 = (lane < 30) ? lane : 29;        // lanes 30/31 mirror lane 29
    const int e    = r10 / 10;
    const int rr   = r10 - e * 10;
    const int half = rr / 5;                  // 0: (i,g)  1: (f,o)
    const int sub  = rr - half * 5;

    const int base = blockIdx.x * EPW;
    const int gb   = base + e;

    // ---- per-lane packed weights ----
    const int r0 = sub + half * 5;            // i_sub or f_sub
    const int r1 = sub + 10 + half * 5;       // g_sub or o_sub
    const float sxlo = 0.5f;
    const float sxhi = half ? 0.5f  : 1.0f;
    const float shlo = 0.25f;
    const float shhi = half ? 0.25f : 0.5f;

    ull wx[5], wh[5];
#pragma unroll
    for (int k = 0; k < 5; ++k) {
        wx[k] = pack2(sxlo * W_ih[r0 * 5 + k], sxhi * W_ih[r1 * 5 + k]);
        wh[k] = pack2(shlo * W_hh[r0 * 5 + k], shhi * W_hh[r1 * 5 + k]);
    }
    const ull bias = pack2(sxlo * (b_ih[r0] + b_hh[r0]),
                           sxhi * (b_ih[r1] + b_hh[r1]));

    // shfl sources
    const int hsrc = e * 10 + 5;              // h lives on half1 lanes
    const int psrc = e * 10 + sub;            // p lives on half0 lanes

    // ---- head weights to smem (one-time) ----
    for (int i = lane; i < 160; i += BLOCK) sW1[i] = W1[i];
    for (int i = lane; i < 1024; i += BLOCK) sW2[(i >> 5) * 33 + (i & 31)] = W2[i];
    for (int i = lane; i < 160; i += BLOCK) sW3[(i >> 5) * 33 + (i & 31)] = W3[i];
    if (lane < 32) { sb1[lane] = b1[lane]; sb2[lane] = b2[lane]; }
    if (lane < 5)  sb3[lane] = b3[lane];

    // ---- staging helpers: each lane covers float4 idx {lane, lane+32} of 60 ----
    const int i0 = lane,  e0 = i0 / 20, q0 = i0 - e0 * 20;
    const int i1 = lane + 32;
    const int e1 = i1 / 20, q1 = i1 - e1 * 20;
    const bool v1 = (i1 < Q4);
    const float4 z4 = make_float4(0.f, 0.f, 0.f, 0.f);

    // stage chunk 0
    {
        float4 p0 = (base + e0 < Bb) ?
            *(const float4*)(x + (base + e0) * ROWF + q0 * 4) : z4;
        float4 p1 = (v1 && base + e1 < Bb) ?
            *(const float4*)(x + (base + e1) * ROWF + q1 * 4) : z4;
        const float* a0 = &p0.x; const float* a1 = &p1.x;
#pragma unroll
        for (int j = 0; j < 4; ++j) {
            int f = q0 * 4 + j; sx[0][f / 5][e0][f % 5] = pack2(a0[j], a0[j]);
        }
        if (v1) {
#pragma unroll
            for (int j = 0; j < 4; ++j) {
                int f = q1 * 4 + j; sx[0][f / 5][e1][f % 5] = pack2(a1[j], a1[j]);
            }
        }
    }
    __syncwarp();

    float c  = 0.0f;
    float hs = 0.0f;                           // 2*h (meaningful on half1)

    for (int ch = 0; ch < NCHUNK; ++ch) {
        // prefetch next chunk into registers
        float4 p0 = z4, p1 = z4;
        if (ch + 1 < NCHUNK) {
            const int off = (ch + 1) * CH_FL;
            if (base + e0 < Bb)
                p0 = *(const float4*)(x + (base + e0) * ROWF + off + q0 * 4);
            if (v1 && base + e1 < Bb)
                p1 = *(const float4*)(x + (base + e1) * ROWF + off + q1 * 4);
        }

        const int buf = ch & 1;
#pragma unroll
        for (int tl = 0; tl < CHUNK; ++tl) {
            const ull* xr = &sx[buf][tl][e][0];
            ull acc = bias;
#pragma unroll
            for (int k = 0; k < 5; ++k) {
                const float hk = __shfl_sync(FULLMASK, hs, hsrc + k);
                acc = fma2(wh[k], pack2(hk, hk), acc);
            }
#pragma unroll
            for (int k = 0; k < 5; ++k)
                acc = fma2(wx[k], xr[k], acc);      // (xA,xA) LDS.64

            float z0, z1; unpack2(acc, z0, z1);
            const float T0 = tanh_fast(z0);         // Ti | Tf
            const float T1 = tanh_fast(z1);         // Tg | To
            const float p  = fmaf(T0, T1, T1);      // half0: 2*i*g
            const float pp = __shfl_sync(FULLMASK, p, psrc);
            const float u  = fmaf(T0, c, c);        // half1: 2*f*c
            c = fmaf(0.5f, u, 0.5f * pp);           // half1: new c
            const float Tc = tanh_fast(c);
            hs = fmaf(T1, Tc, Tc);                  // half1: new 2*h
        }

        if (ch + 1 < NCHUNK) {
            const int nb = (ch + 1) & 1;
            const float* a0 = &p0.x; const float* a1 = &p1.x;
#pragma unroll
            for (int j = 0; j < 4; ++j) {
                int f = q0 * 4 + j; sx[nb][f / 5][e0][f % 5] = pack2(a0[j], a0[j]);
            }
            if (v1) {
#pragma unroll
                for (int j = 0; j < 4; ++j) {
                    int f = q1 * 4 + j; sx[nb][f / 5][e1][f % 5] = pack2(a1[j], a1[j]);
                }
            }
        }
        __syncwarp();
    }

    // ==================== fused head ====================
    if (lane < 30 && half == 1 && gb < Bb)
        hres[e * Hh + sub] = 0.5f * hs + x[gb * ROWF + (Tt - 1) * Hh + sub];
    __syncwarp();

#pragma unroll
    for (int ee = 0; ee < EPW; ++ee) {
        const int g = base + ee;
        float a1 = sb1[lane];
#pragma unroll
        for (int k = 0; k < 5; ++k)
            a1 = fmaf(sW1[lane * 5 + k], hres[ee * Hh + k], a1);   // LDS bcast
        a1 = fmaxf(a1, 0.0f);

        float a2 = sb2[lane];
#pragma unroll
        for (int k = 0; k < 32; ++k)
            a2 = fmaf(sW2[lane * 33 + k], __shfl_sync(FULLMASK, a1, k), a2);
        a2 = fmaxf(a2, 0.0f);

        const int wrow = (lane < 5) ? lane : 0;
        float o = (lane < 5) ? sb3[lane] : 0.0f;
#pragma unroll
        for (int k = 0; k < 32; ++k)
            o = fmaf(sW3[wrow * 33 + k], __shfl_sync(FULLMASK, a2, k), o);

        if (lane < 5 && g < Bb) out[g * Hh + lane] = o;
    }
}

// ============================================================================
extern "C" void kernel_launch(void* const* d_in, const int* in_sizes, int n_in,
                              void* d_out, int out_size) {
    const float* x    = (const float*)d_in[0];
    const float* W_ih = (const float*)d_in[1];
    const float* W_hh = (const float*)d_in[2];
    const float* b_ih = (const float*)d_in[3];
    const float* b_hh = (const float*)d_in[4];
    const float* W1   = (const float*)d_in[5];
    const float* b1   = (const float*)d_in[6];
    const float* W2   = (const float*)d_in[7];
    const float* b2   = (const float*)d_in[8];
    const float* W3   = (const float*)d_in[9];
    const float* b3   = (const float*)d_in[10];
    float* out = (float*)d_out;

    fused_kernel<<<GRID, BLOCK>>>(x, W_ih, W_hh, b_ih, b_hh,
                                  W1, b1, W2, b2, W3, b3, out);
    (void)in_sizes; (void)n_in; (void)out_size;
}